// round 7
// baseline (speedup 1.0000x reference)
#include <cuda_runtime.h>
#include <cuda_bf16.h>
#include <cuda_fp16.h>
#include <cstdint>

#define N_NODES 50000
#define D 128
#define E_MAX 800000

// ---------------- device scratch (static, no allocation) -------------------
__device__ __half g_y[(size_t)N_NODES * D];       // x @ W^T in fp16 (12.8 MB)
__device__ int    g_cnt[N_NODES];                 // zeroed at end of each call
__device__ int    g_off[N_NODES + 1];
__device__ int    g_cur[N_NODES];
__device__ int2   g_sedge[E_MAX];                 // row-sorted (col, w_bits)

// ---------------------------------------------------------------------------
// tf32 mma helpers
// ---------------------------------------------------------------------------
__device__ __forceinline__ unsigned f2tf32(float f) {
    unsigned u;
    asm("cvt.rna.tf32.f32 %0, %1;" : "=r"(u) : "f"(f));
    return u;
}

__device__ __forceinline__ void mma_tf32(float* c, const unsigned* a,
                                         unsigned b0, unsigned b1) {
    asm volatile(
        "mma.sync.aligned.m16n8k8.row.col.f32.tf32.tf32.f32 "
        "{%0,%1,%2,%3}, {%4,%5,%6,%7}, {%8,%9}, {%0,%1,%2,%3};\n"
        : "+f"(c[0]), "+f"(c[1]), "+f"(c[2]), "+f"(c[3])
        : "r"(a[0]), "r"(a[1]), "r"(a[2]), "r"(a[3]), "r"(b0), "r"(b1));
}

#define LD 132
#define GEMM_THREADS 512
#define HIST_BLOCKS 64

// ---------------------------------------------------------------------------
// Kernel A: fused  (a) y = x @ W^T (tf32 tensor cores, fp16 output)
//                  (b) edge-row histogram (extra blocks, hides under GEMM)
// ---------------------------------------------------------------------------
__global__ void gemm_hist(const float* __restrict__ x,
                          const float* __restrict__ W,
                          __half* __restrict__ yh,
                          const int* __restrict__ erow,
                          int* __restrict__ cnt,
                          int n, int E, int gemm_blocks) {
    if (blockIdx.x >= gemm_blocks) {
        // ---- histogram part ----
        int stride = HIST_BLOCKS * GEMM_THREADS;
        int start = (blockIdx.x - gemm_blocks) * GEMM_THREADS + threadIdx.x;
        for (int e = start; e < E; e += stride)
            atomicAdd(&cnt[__ldg(erow + e)], 1);
        return;
    }

    // ---- GEMM part: 128x128 tile, 16 warps (4x4), warp tile 32x32 ----
    extern __shared__ unsigned smem_u[];
    unsigned* As = smem_u;              // [128][LD]
    unsigned* Bs = smem_u + 128 * LD;   // [128][LD]

    int tid = threadIdx.x;
    int row0 = blockIdx.x * 128;

    for (int i = tid; i < (D * D) / 4; i += GEMM_THREADS) {
        int r = (i * 4) >> 7, c = (i * 4) & 127;
        float4 v = ((const float4*)W)[i];
        unsigned* p = &Bs[r * LD + c];
        p[0] = f2tf32(v.x); p[1] = f2tf32(v.y);
        p[2] = f2tf32(v.z); p[3] = f2tf32(v.w);
    }
    for (int i = tid; i < (128 * D) / 4; i += GEMM_THREADS) {
        int r = (i * 4) >> 7, c = (i * 4) & 127;
        int gr = row0 + r;
        float4 v = (gr < n) ? ((const float4*)(x + (size_t)gr * D))[c >> 2]
                            : make_float4(0.f, 0.f, 0.f, 0.f);
        unsigned* p = &As[r * LD + c];
        p[0] = f2tf32(v.x); p[1] = f2tf32(v.y);
        p[2] = f2tf32(v.z); p[3] = f2tf32(v.w);
    }
    __syncthreads();

    int warp = tid >> 5, lane = tid & 31;
    int wm = warp & 3, wn = warp >> 2;
    int m0 = wm * 32, n0 = wn * 32;
    int grp = lane >> 2, tg = lane & 3;

    float acc[2][4][4];
    #pragma unroll
    for (int mt = 0; mt < 2; mt++)
        #pragma unroll
        for (int nt = 0; nt < 4; nt++)
            #pragma unroll
            for (int q = 0; q < 4; q++) acc[mt][nt][q] = 0.f;

    #pragma unroll
    for (int k0 = 0; k0 < D; k0 += 8) {
        unsigned a[2][4];
        #pragma unroll
        for (int mt = 0; mt < 2; mt++) {
            int r = m0 + mt * 16 + grp;
            a[mt][0] = As[r * LD + k0 + tg];
            a[mt][1] = As[(r + 8) * LD + k0 + tg];
            a[mt][2] = As[r * LD + k0 + tg + 4];
            a[mt][3] = As[(r + 8) * LD + k0 + tg + 4];
        }
        #pragma unroll
        for (int nt = 0; nt < 4; nt++) {
            int nr = n0 + nt * 8 + grp;
            unsigned b0 = Bs[nr * LD + k0 + tg];
            unsigned b1 = Bs[nr * LD + k0 + tg + 4];
            mma_tf32(acc[0][nt], a[0], b0, b1);
            mma_tf32(acc[1][nt], a[1], b0, b1);
        }
    }

    #pragma unroll
    for (int mt = 0; mt < 2; mt++)
        #pragma unroll
        for (int nt = 0; nt < 4; nt++) {
            int r = row0 + m0 + mt * 16 + grp;
            int c = n0 + nt * 8 + tg * 2;
            if (r < n)
                *(__half2*)&yh[(size_t)r * D + c] =
                    __floats2half2_rn(acc[mt][nt][0], acc[mt][nt][1]);
            if (r + 8 < n)
                *(__half2*)&yh[(size_t)(r + 8) * D + c] =
                    __floats2half2_rn(acc[mt][nt][2], acc[mt][nt][3]);
        }
}

// ---------------------------------------------------------------------------
// Kernel B: single-block full scan. 1024 threads, contiguous chunks.
// Writes off[] and cur[], zeroes cnt[] for the next call.
// ---------------------------------------------------------------------------
__device__ __forceinline__ int warp_incl_scan(int v, int lane) {
    #pragma unroll
    for (int o = 1; o < 32; o <<= 1) {
        int u = __shfl_up_sync(0xFFFFFFFFu, v, o);
        if (lane >= o) v += u;
    }
    return v;
}

#define SCAN_T 1024

__global__ void fullscan(int* __restrict__ cnt, int* __restrict__ off,
                         int* __restrict__ cur, int n, int E) {
    __shared__ int ws[32];
    int t = threadIdx.x;
    int lane = t & 31, wid = t >> 5;
    int chunk = (n + SCAN_T - 1) / SCAN_T;
    int s0 = t * chunk;
    int s1 = min(s0 + chunk, n);

    int sum = 0;
    for (int i = s0; i < s1; i++) sum += cnt[i];

    int v = warp_incl_scan(sum, lane);
    if (lane == 31) ws[wid] = v;
    __syncthreads();
    if (wid == 0) {
        int s = ws[lane];
        s = warp_incl_scan(s, lane);
        ws[lane] = s;
    }
    __syncthreads();
    int run = (wid > 0 ? ws[wid - 1] : 0) + v - sum;   // exclusive prefix

    for (int i = s0; i < s1; i++) {
        int c = cnt[i];
        off[i] = run;
        cur[i] = run;
        cnt[i] = 0;                 // reset for next call
        run += c;
    }
    if (t == SCAN_T - 1) off[n] = E;
}

// ---------------------------------------------------------------------------
// Kernel C: permute edges into row-sorted order.
// ---------------------------------------------------------------------------
__global__ void permute(const int* __restrict__ erow, const int* __restrict__ ecol,
                        const float* __restrict__ ew, int* __restrict__ cur,
                        int2* __restrict__ sedge, int E) {
    int e = blockIdx.x * blockDim.x + threadIdx.x;
    if (e < E) {
        int r = erow[e];
        int p = atomicAdd(&cur[r], 1);
        sedge[p] = make_int2(ecol[e], __float_as_int(ew[e]));
    }
}

// ---------------------------------------------------------------------------
// Kernel D: gather. One warp per node; lane l owns halfs [4l, 4l+3] (8 B).
// out[node] = b + sum_e w_e * y_fp16[col_e]   (fp32 accumulate, single store)
// ---------------------------------------------------------------------------
__global__ void gather(const uint2* __restrict__ y2,
                       const int* __restrict__ off,
                       const int2* __restrict__ sedge,
                       const float* __restrict__ b,
                       float4* __restrict__ out4, int n) {
    int node = (blockIdx.x * blockDim.x + threadIdx.x) >> 5;
    int lane = threadIdx.x & 31;
    if (node >= n) return;

    int s = off[node];
    int e = off[node + 1];

    float4 acc = ((const float4*)b)[lane];

    for (int i = s; i < e; i += 32) {
        int j = i + lane;
        int2 ed = (j < e) ? sedge[j] : make_int2(0, 0);
        int cnt = min(32, e - i);
        #pragma unroll 4
        for (int t = 0; t < cnt; t++) {
            int col = __shfl_sync(0xFFFFFFFFu, ed.x, t);
            float w = __int_as_float(__shfl_sync(0xFFFFFFFFu, ed.y, t));
            uint2 raw = y2[(size_t)col * 32 + lane];
            float2 lo = __half22float2(*(const __half2*)&raw.x);
            float2 hi = __half22float2(*(const __half2*)&raw.y);
            acc.x += w * lo.x;
            acc.y += w * lo.y;
            acc.z += w * hi.x;
            acc.w += w * hi.y;
        }
    }
    out4[(size_t)node * 32 + lane] = acc;
}

// ---------------------------------------------------------------------------
extern "C" void kernel_launch(void* const* d_in, const int* in_sizes, int n_in,
                              void* d_out, int out_size) {
    const float* x    = (const float*)d_in[0];
    const int*   erow = (const int*)d_in[1];
    const int*   ecol = (const int*)d_in[2];
    const float* ew   = (const float*)d_in[3];
    const float* W    = (const float*)d_in[4];
    const float* b    = (const float*)d_in[5];
    float* out = (float*)d_out;

    int n = in_sizes[0] / D;     // 50000
    int E = in_sizes[1];         // 800000

    __half* yh;  cudaGetSymbolAddress((void**)&yh, g_y);
    int* cnt;    cudaGetSymbolAddress((void**)&cnt, g_cnt);
    int* off;    cudaGetSymbolAddress((void**)&off, g_off);
    int* cur;    cudaGetSymbolAddress((void**)&cur, g_cur);
    int2* sedge; cudaGetSymbolAddress((void**)&sedge, g_sedge);

    // --- A: GEMM (tf32 -> fp16 y) + fused histogram ---
    const int smem_bytes = 2 * 128 * LD * (int)sizeof(unsigned);  // ~135 KB
    cudaFuncSetAttribute(gemm_hist, cudaFuncAttributeMaxDynamicSharedMemorySize,
                         smem_bytes);
    int gblocks = (n + 127) / 128;
    gemm_hist<<<gblocks + HIST_BLOCKS, GEMM_THREADS, smem_bytes>>>(
        x, W, yh, erow, cnt, n, E, gblocks);

    // --- B: single-block scan (also zeroes cnt for next call) ---
    fullscan<<<1, SCAN_T>>>(cnt, off, cur, n, E);

    // --- C: permute into row-sorted edge array ---
    permute<<<(E + 511) / 512, 512>>>(erow, ecol, ew, cur, sedge, E);

    // --- D: gather (one warp per node), fused bias + single store ---
    int gthreads = 512;
    int gwpb = gthreads / 32;
    int gblocks2 = (n + gwpb - 1) / gwpb;
    gather<<<gblocks2, gthreads>>>((const uint2*)yh, off, sedge, b,
                                   (float4*)out, n);
}

// round 8
// speedup vs baseline: 1.5169x; 1.5169x over previous
#include <cuda_runtime.h>
#include <cuda_bf16.h>
#include <cuda_fp16.h>
#include <cstdint>

#define N_NODES 50000
#define D 128
#define E_MAX 800000

// ---------------- device scratch (static, no allocation) -------------------
__device__ __half g_y[(size_t)N_NODES * D];       // x @ W^T in fp16 (12.8 MB)
__device__ int    g_cnt[N_NODES];                 // zeroed by fullscan each call
__device__ int    g_off[N_NODES + 1];
__device__ int    g_cur[N_NODES];
__device__ int2   g_sedge[E_MAX];                 // row-sorted (col, w_bits)

// ---------------------------------------------------------------------------
// tf32 mma helpers
// ---------------------------------------------------------------------------
__device__ __forceinline__ unsigned f2tf32(float f) {
    unsigned u;
    asm("cvt.rna.tf32.f32 %0, %1;" : "=r"(u) : "f"(f));
    return u;
}

__device__ __forceinline__ void mma_tf32(float* c, const unsigned* a,
                                         unsigned b0, unsigned b1) {
    asm volatile(
        "mma.sync.aligned.m16n8k8.row.col.f32.tf32.tf32.f32 "
        "{%0,%1,%2,%3}, {%4,%5,%6,%7}, {%8,%9}, {%0,%1,%2,%3};\n"
        : "+f"(c[0]), "+f"(c[1]), "+f"(c[2]), "+f"(c[3])
        : "r"(a[0]), "r"(a[1]), "r"(a[2]), "r"(a[3]), "r"(b0), "r"(b1));
}

#define LD 132
#define GEMM_THREADS 512
#define HIST_BLOCKS 64

// ---------------------------------------------------------------------------
// Kernel A: fused  (a) y = x @ W^T (tf32 tensor cores, fp16 output)
//                  (b) edge-row histogram (tail blocks)
// ---------------------------------------------------------------------------
__global__ void gemm_hist(const float* __restrict__ x,
                          const float* __restrict__ W,
                          __half* __restrict__ yh,
                          const int* __restrict__ erow,
                          int* __restrict__ cnt,
                          int n, int E, int gemm_blocks) {
    if (blockIdx.x >= gemm_blocks) {
        int stride = HIST_BLOCKS * GEMM_THREADS;
        int start = (blockIdx.x - gemm_blocks) * GEMM_THREADS + threadIdx.x;
        for (int e = start; e < E; e += stride)
            atomicAdd(&cnt[__ldg(erow + e)], 1);
        return;
    }

    // ---- GEMM: 128x128 tile, 16 warps (4x4), warp tile 32x32 ----
    extern __shared__ unsigned smem_u[];
    unsigned* As = smem_u;              // [128][LD]
    unsigned* Bs = smem_u + 128 * LD;   // [128][LD]

    int tid = threadIdx.x;
    int row0 = blockIdx.x * 128;

    for (int i = tid; i < (D * D) / 4; i += GEMM_THREADS) {
        int r = (i * 4) >> 7, c = (i * 4) & 127;
        float4 v = ((const float4*)W)[i];
        unsigned* p = &Bs[r * LD + c];
        p[0] = f2tf32(v.x); p[1] = f2tf32(v.y);
        p[2] = f2tf32(v.z); p[3] = f2tf32(v.w);
    }
    for (int i = tid; i < (128 * D) / 4; i += GEMM_THREADS) {
        int r = (i * 4) >> 7, c = (i * 4) & 127;
        int gr = row0 + r;
        float4 v = (gr < n) ? ((const float4*)(x + (size_t)gr * D))[c >> 2]
                            : make_float4(0.f, 0.f, 0.f, 0.f);
        unsigned* p = &As[r * LD + c];
        p[0] = f2tf32(v.x); p[1] = f2tf32(v.y);
        p[2] = f2tf32(v.z); p[3] = f2tf32(v.w);
    }
    __syncthreads();

    int warp = tid >> 5, lane = tid & 31;
    int wm = warp & 3, wn = warp >> 2;
    int m0 = wm * 32, n0 = wn * 32;
    int grp = lane >> 2, tg = lane & 3;

    float acc[2][4][4];
    #pragma unroll
    for (int mt = 0; mt < 2; mt++)
        #pragma unroll
        for (int nt = 0; nt < 4; nt++)
            #pragma unroll
            for (int q = 0; q < 4; q++) acc[mt][nt][q] = 0.f;

    #pragma unroll
    for (int k0 = 0; k0 < D; k0 += 8) {
        unsigned a[2][4];
        #pragma unroll
        for (int mt = 0; mt < 2; mt++) {
            int r = m0 + mt * 16 + grp;
            a[mt][0] = As[r * LD + k0 + tg];
            a[mt][1] = As[(r + 8) * LD + k0 + tg];
            a[mt][2] = As[r * LD + k0 + tg + 4];
            a[mt][3] = As[(r + 8) * LD + k0 + tg + 4];
        }
        #pragma unroll
        for (int nt = 0; nt < 4; nt++) {
            int nr = n0 + nt * 8 + grp;
            unsigned b0 = Bs[nr * LD + k0 + tg];
            unsigned b1 = Bs[nr * LD + k0 + tg + 4];
            mma_tf32(acc[0][nt], a[0], b0, b1);
            mma_tf32(acc[1][nt], a[1], b0, b1);
        }
    }

    #pragma unroll
    for (int mt = 0; mt < 2; mt++)
        #pragma unroll
        for (int nt = 0; nt < 4; nt++) {
            int r = row0 + m0 + mt * 16 + grp;
            int c = n0 + nt * 8 + tg * 2;
            if (r < n)
                *(__half2*)&yh[(size_t)r * D + c] =
                    __floats2half2_rn(acc[mt][nt][0], acc[mt][nt][1]);
            if (r + 8 < n)
                *(__half2*)&yh[(size_t)(r + 8) * D + c] =
                    __floats2half2_rn(acc[mt][nt][2], acc[mt][nt][3]);
        }
}

// ---------------------------------------------------------------------------
// Kernel B: single-block TILED scan — fully coalesced.
// 49 tiles of 1024 contiguous elements; warp shfl-scan + cross-warp combine
// + running carry in smem. Also zeroes cnt[] for the next call.
// ---------------------------------------------------------------------------
__device__ __forceinline__ int warp_incl_scan(int v, int lane) {
    #pragma unroll
    for (int o = 1; o < 32; o <<= 1) {
        int u = __shfl_up_sync(0xFFFFFFFFu, v, o);
        if (lane >= o) v += u;
    }
    return v;
}

#define SCAN_T 1024

__global__ void fullscan(int* __restrict__ cnt, int* __restrict__ off,
                         int* __restrict__ cur, int n, int E) {
    __shared__ int ws[32];
    __shared__ int carry;
    int t = threadIdx.x;
    int lane = t & 31, wid = t >> 5;
    if (t == 0) carry = 0;
    __syncthreads();

    for (int base = 0; base < n; base += SCAN_T) {
        int i = base + t;
        int c = (i < n) ? cnt[i] : 0;

        int v = warp_incl_scan(c, lane);
        if (lane == 31) ws[wid] = v;
        __syncthreads();
        if (wid == 0) {
            int s = ws[lane];
            s = warp_incl_scan(s, lane);
            ws[lane] = s;
        }
        __syncthreads();

        int excl = carry + (wid > 0 ? ws[wid - 1] : 0) + v - c;
        if (i < n) {
            off[i] = excl;
            cur[i] = excl;
            cnt[i] = 0;                // reset for next call
        }
        __syncthreads();               // everyone done reading carry/ws
        if (t == 0) carry += ws[31];   // add tile total
        __syncthreads();
    }
    if (t == 0) off[n] = E;
}

// ---------------------------------------------------------------------------
// Kernel C: permute edges into row-sorted order.
// ---------------------------------------------------------------------------
__global__ void permute(const int* __restrict__ erow, const int* __restrict__ ecol,
                        const float* __restrict__ ew, int* __restrict__ cur,
                        int2* __restrict__ sedge, int E) {
    int e = blockIdx.x * blockDim.x + threadIdx.x;
    if (e < E) {
        int r = erow[e];
        int p = atomicAdd(&cur[r], 1);
        sedge[p] = make_int2(ecol[e], __float_as_int(ew[e]));
    }
}

// ---------------------------------------------------------------------------
// Kernel D: gather. One warp per node; lane l owns halfs [4l, 4l+3] (8 B).
// out[node] = b + sum_e w_e * y_fp16[col_e]   (fp32 accumulate, single store)
// ---------------------------------------------------------------------------
__global__ void gather(const uint2* __restrict__ y2,
                       const int* __restrict__ off,
                       const int2* __restrict__ sedge,
                       const float* __restrict__ b,
                       float4* __restrict__ out4, int n) {
    int node = (blockIdx.x * blockDim.x + threadIdx.x) >> 5;
    int lane = threadIdx.x & 31;
    if (node >= n) return;

    int s = off[node];
    int e = off[node + 1];

    float4 acc = ((const float4*)b)[lane];

    for (int i = s; i < e; i += 32) {
        int j = i + lane;
        int2 ed = (j < e) ? sedge[j] : make_int2(0, 0);
        int cnt = min(32, e - i);
        #pragma unroll 4
        for (int t = 0; t < cnt; t++) {
            int col = __shfl_sync(0xFFFFFFFFu, ed.x, t);
            float w = __int_as_float(__shfl_sync(0xFFFFFFFFu, ed.y, t));
            uint2 raw = y2[(size_t)col * 32 + lane];
            float2 lo = __half22float2(*(const __half2*)&raw.x);
            float2 hi = __half22float2(*(const __half2*)&raw.y);
            acc.x += w * lo.x;
            acc.y += w * lo.y;
            acc.z += w * hi.x;
            acc.w += w * hi.y;
        }
    }
    out4[(size_t)node * 32 + lane] = acc;
}

// ---------------------------------------------------------------------------
extern "C" void kernel_launch(void* const* d_in, const int* in_sizes, int n_in,
                              void* d_out, int out_size) {
    const float* x    = (const float*)d_in[0];
    const int*   erow = (const int*)d_in[1];
    const int*   ecol = (const int*)d_in[2];
    const float* ew   = (const float*)d_in[3];
    const float* W    = (const float*)d_in[4];
    const float* b    = (const float*)d_in[5];
    float* out = (float*)d_out;

    int n = in_sizes[0] / D;     // 50000
    int E = in_sizes[1];         // 800000

    __half* yh;  cudaGetSymbolAddress((void**)&yh, g_y);
    int* cnt;    cudaGetSymbolAddress((void**)&cnt, g_cnt);
    int* off;    cudaGetSymbolAddress((void**)&off, g_off);
    int* cur;    cudaGetSymbolAddress((void**)&cur, g_cur);
    int2* sedge; cudaGetSymbolAddress((void**)&sedge, g_sedge);

    // --- A: GEMM (tf32 -> fp16 y) + fused histogram ---
    const int smem_bytes = 2 * 128 * LD * (int)sizeof(unsigned);  // ~135 KB
    cudaFuncSetAttribute(gemm_hist, cudaFuncAttributeMaxDynamicSharedMemorySize,
                         smem_bytes);
    int gblocks = (n + 127) / 128;
    gemm_hist<<<gblocks + HIST_BLOCKS, GEMM_THREADS, smem_bytes>>>(
        x, W, yh, erow, cnt, n, E, gblocks);

    // --- B: single-block tiled coalesced scan (also zeroes cnt) ---
    fullscan<<<1, SCAN_T>>>(cnt, off, cur, n, E);

    // --- C: permute into row-sorted edge array ---
    permute<<<(E + 511) / 512, 512>>>(erow, ecol, ew, cur, sedge, E);

    // --- D: gather (one warp per node), fused bias + single store ---
    int gthreads = 512;
    int gwpb = gthreads / 32;
    int gblocks2 = (n + gwpb - 1) / gwpb;
    gather<<<gblocks2, gthreads>>>((const uint2*)yh, off, sedge, b,
                                   (float4*)out, n);
}

// round 11
// speedup vs baseline: 1.5541x; 1.0245x over previous
#include <cuda_runtime.h>
#include <cuda_bf16.h>
#include <cuda_fp16.h>
#include <cstdint>

#define N_NODES 50000
#define D 128
#define E_MAX 800000

// ---------------- device scratch (static, no allocation) -------------------
__device__ __half g_y[(size_t)N_NODES * D];       // x @ W^T in fp16 (12.8 MB)
__device__ int    g_cnt[N_NODES];                 // zeroed by fullscan each call
__device__ int    g_off[N_NODES + 1];
__device__ int    g_cur[N_NODES];
__device__ int2   g_sedge[E_MAX];                 // row-sorted (col, w_bits)

// ---------------------------------------------------------------------------
// tf32 mma helpers
// ---------------------------------------------------------------------------
__device__ __forceinline__ unsigned f2tf32(float f) {
    unsigned u;
    asm("cvt.rna.tf32.f32 %0, %1;" : "=r"(u) : "f"(f));
    return u;
}

__device__ __forceinline__ void mma_tf32(float* c, const unsigned* a,
                                         unsigned b0, unsigned b1) {
    asm volatile(
        "mma.sync.aligned.m16n8k8.row.col.f32.tf32.tf32.f32 "
        "{%0,%1,%2,%3}, {%4,%5,%6,%7}, {%8,%9}, {%0,%1,%2,%3};\n"
        : "+f"(c[0]), "+f"(c[1]), "+f"(c[2]), "+f"(c[3])
        : "r"(a[0]), "r"(a[1]), "r"(a[2]), "r"(a[3]), "r"(b0), "r"(b1));
}

#define LD 132
#define GEMM_THREADS 512
#define HIST_BLOCKS 64

// ---------------------------------------------------------------------------
// Kernel A: fused  (a) edge-row histogram  -- FIRST 64 blocks (wave 1, overlaps)
//                  (b) y = x @ W^T (tf32 tensor cores, fp16 output)
// ---------------------------------------------------------------------------
__global__ void gemm_hist(const float* __restrict__ x,
                          const float* __restrict__ W,
                          __half* __restrict__ yh,
                          const int* __restrict__ erow,
                          int* __restrict__ cnt,
                          int n, int E) {
    if (blockIdx.x < HIST_BLOCKS) {
        // ---- histogram: runs in the first wave, hidden under the GEMM ----
        int stride = HIST_BLOCKS * GEMM_THREADS;
        int start = blockIdx.x * GEMM_THREADS + threadIdx.x;
        for (int e = start; e < E; e += stride)
            atomicAdd(&cnt[__ldg(erow + e)], 1);
        return;
    }

    // ---- GEMM: 128x128 tile, 16 warps (4x4), warp tile 32x32 ----
    extern __shared__ unsigned smem_u[];
    unsigned* As = smem_u;              // [128][LD]
    unsigned* Bs = smem_u + 128 * LD;   // [128][LD]

    int tid = threadIdx.x;
    int row0 = (blockIdx.x - HIST_BLOCKS) * 128;

    for (int i = tid; i < (D * D) / 4; i += GEMM_THREADS) {
        int r = (i * 4) >> 7, c = (i * 4) & 127;
        float4 v = ((const float4*)W)[i];
        unsigned* p = &Bs[r * LD + c];
        p[0] = f2tf32(v.x); p[1] = f2tf32(v.y);
        p[2] = f2tf32(v.z); p[3] = f2tf32(v.w);
    }
    for (int i = tid; i < (128 * D) / 4; i += GEMM_THREADS) {
        int r = (i * 4) >> 7, c = (i * 4) & 127;
        int gr = row0 + r;
        float4 v = (gr < n) ? ((const float4*)(x + (size_t)gr * D))[c >> 2]
                            : make_float4(0.f, 0.f, 0.f, 0.f);
        unsigned* p = &As[r * LD + c];
        p[0] = f2tf32(v.x); p[1] = f2tf32(v.y);
        p[2] = f2tf32(v.z); p[3] = f2tf32(v.w);
    }
    __syncthreads();

    int warp = tid >> 5, lane = tid & 31;
    int wm = warp & 3, wn = warp >> 2;
    int m0 = wm * 32, n0 = wn * 32;
    int grp = lane >> 2, tg = lane & 3;

    float acc[2][4][4];
    #pragma unroll
    for (int mt = 0; mt < 2; mt++)
        #pragma unroll
        for (int nt = 0; nt < 4; nt++)
            #pragma unroll
            for (int q = 0; q < 4; q++) acc[mt][nt][q] = 0.f;

    #pragma unroll
    for (int k0 = 0; k0 < D; k0 += 8) {
        unsigned a[2][4];
        #pragma unroll
        for (int mt = 0; mt < 2; mt++) {
            int r = m0 + mt * 16 + grp;
            a[mt][0] = As[r * LD + k0 + tg];
            a[mt][1] = As[(r + 8) * LD + k0 + tg];
            a[mt][2] = As[r * LD + k0 + tg + 4];
            a[mt][3] = As[(r + 8) * LD + k0 + tg + 4];
        }
        #pragma unroll
        for (int nt = 0; nt < 4; nt++) {
            int nr = n0 + nt * 8 + grp;
            unsigned b0 = Bs[nr * LD + k0 + tg];
            unsigned b1 = Bs[nr * LD + k0 + tg + 4];
            mma_tf32(acc[0][nt], a[0], b0, b1);
            mma_tf32(acc[1][nt], a[1], b0, b1);
        }
    }

    #pragma unroll
    for (int mt = 0; mt < 2; mt++)
        #pragma unroll
        for (int nt = 0; nt < 4; nt++) {
            int r = row0 + m0 + mt * 16 + grp;
            int c = n0 + nt * 8 + tg * 2;
            if (r < n)
                *(__half2*)&yh[(size_t)r * D + c] =
                    __floats2half2_rn(acc[mt][nt][0], acc[mt][nt][1]);
            if (r + 8 < n)
                *(__half2*)&yh[(size_t)(r + 8) * D + c] =
                    __floats2half2_rn(acc[mt][nt][2], acc[mt][nt][3]);
        }
}

// ---------------------------------------------------------------------------
// Kernel B: single-block TILED scan — fully coalesced tiles of 1024.
// Writes off[] and cur[], zeroes cnt[] for the next call.
// ---------------------------------------------------------------------------
__device__ __forceinline__ int warp_incl_scan(int v, int lane) {
    #pragma unroll
    for (int o = 1; o < 32; o <<= 1) {
        int u = __shfl_up_sync(0xFFFFFFFFu, v, o);
        if (lane >= o) v += u;
    }
    return v;
}

#define SCAN_T 1024

__global__ void fullscan(int* __restrict__ cnt, int* __restrict__ off,
                         int* __restrict__ cur, int n, int E) {
    __shared__ int ws[32];
    __shared__ int carry;
    int t = threadIdx.x;
    int lane = t & 31, wid = t >> 5;
    if (t == 0) carry = 0;
    __syncthreads();

    for (int base = 0; base < n; base += SCAN_T) {
        int i = base + t;
        int c = (i < n) ? cnt[i] : 0;

        int v = warp_incl_scan(c, lane);
        if (lane == 31) ws[wid] = v;
        __syncthreads();
        if (wid == 0) {
            int s = ws[lane];
            s = warp_incl_scan(s, lane);
            ws[lane] = s;
        }
        __syncthreads();

        int excl = carry + (wid > 0 ? ws[wid - 1] : 0) + v - c;
        if (i < n) {
            off[i] = excl;
            cur[i] = excl;
            cnt[i] = 0;                // reset for next call
        }
        __syncthreads();
        if (t == 0) carry += ws[31];
        __syncthreads();
    }
    if (t == 0) off[n] = E;
}

// ---------------------------------------------------------------------------
// Kernel C: permute edges into row-sorted order.
// ---------------------------------------------------------------------------
__global__ void permute(const int* __restrict__ erow, const int* __restrict__ ecol,
                        const float* __restrict__ ew, int* __restrict__ cur,
                        int2* __restrict__ sedge, int E) {
    int e = blockIdx.x * blockDim.x + threadIdx.x;
    if (e < E) {
        int r = erow[e];
        int p = atomicAdd(&cur[r], 1);
        sedge[p] = make_int2(ecol[e], __float_as_int(ew[e]));
    }
}

// ---------------------------------------------------------------------------
// Kernel D: split-warp gather. One warp per node; 16 lanes per edge,
// TWO edges per inner iteration (half = lane>>4 selects even/odd edge).
// fp16 row = 256 B = 16 uint4 chunks; lane sub owns chunk sub (8 halfs).
// Final: xor-16 combine, half 0 adds bias and stores the fp32 row.
// ---------------------------------------------------------------------------
__global__ void gather(const uint4* __restrict__ y4h,
                       const int* __restrict__ off,
                       const int2* __restrict__ sedge,
                       const float* __restrict__ b,
                       float4* __restrict__ out4, int n) {
    int node = (blockIdx.x * blockDim.x + threadIdx.x) >> 5;
    int lane = threadIdx.x & 31;
    if (node >= n) return;

    int hf  = lane >> 4;        // 0: even edges, 1: odd edges
    int sub = lane & 15;        // 16-byte chunk within the 256-byte fp16 row

    int s = off[node];
    int e = off[node + 1];

    float acc[8];
    #pragma unroll
    for (int q = 0; q < 8; q++) acc[q] = 0.f;

    for (int i = s; i < e; i += 32) {
        int j = i + lane;
        // padded lanes carry w = 0 -> contribute nothing
        int2 ed = (j < e) ? sedge[j] : make_int2(0, 0);
        int cnt = min(32, e - i);
        int pairs = (cnt + 1) >> 1;
        for (int t = 0; t < pairs; t++) {
            int src = 2 * t + hf;
            int col  = __shfl_sync(0xFFFFFFFFu, ed.x, src);
            float w  = __int_as_float(__shfl_sync(0xFFFFFFFFu, ed.y, src));
            uint4 raw = y4h[(size_t)col * 16 + sub];   // 16 uint4 per row!
            float2 f0 = __half22float2(*(const __half2*)&raw.x);
            float2 f1 = __half22float2(*(const __half2*)&raw.y);
            float2 f2 = __half22float2(*(const __half2*)&raw.z);
            float2 f3 = __half22float2(*(const __half2*)&raw.w);
            acc[0] += w * f0.x;  acc[1] += w * f0.y;
            acc[2] += w * f1.x;  acc[3] += w * f1.y;
            acc[4] += w * f2.x;  acc[5] += w * f2.y;
            acc[6] += w * f3.x;  acc[7] += w * f3.y;
        }
    }

    // combine the two half-warps
    #pragma unroll
    for (int q = 0; q < 8; q++)
        acc[q] += __shfl_xor_sync(0xFFFFFFFFu, acc[q], 16);

    if (hf == 0) {
        // lane sub owns fp32 columns [8*sub, 8*sub+7]
        const float4* b4 = (const float4*)b;
        float4 bv0 = b4[sub * 2];
        float4 bv1 = b4[sub * 2 + 1];
        float4 o0 = make_float4(acc[0] + bv0.x, acc[1] + bv0.y,
                                acc[2] + bv0.z, acc[3] + bv0.w);
        float4 o1 = make_float4(acc[4] + bv1.x, acc[5] + bv1.y,
                                acc[6] + bv1.z, acc[7] + bv1.w);
        out4[(size_t)node * 32 + sub * 2]     = o0;
        out4[(size_t)node * 32 + sub * 2 + 1] = o1;
    }
}

// ---------------------------------------------------------------------------
extern "C" void kernel_launch(void* const* d_in, const int* in_sizes, int n_in,
                              void* d_out, int out_size) {
    const float* x    = (const float*)d_in[0];
    const int*   erow = (const int*)d_in[1];
    const int*   ecol = (const int*)d_in[2];
    const float* ew   = (const float*)d_in[3];
    const float* W    = (const float*)d_in[4];
    const float* b    = (const float*)d_in[5];
    float* out = (float*)d_out;

    int n = in_sizes[0] / D;     // 50000
    int E = in_sizes[1];         // 800000

    __half* yh;  cudaGetSymbolAddress((void**)&yh, g_y);
    int* cnt;    cudaGetSymbolAddress((void**)&cnt, g_cnt);
    int* off;    cudaGetSymbolAddress((void**)&off, g_off);
    int* cur;    cudaGetSymbolAddress((void**)&cur, g_cur);
    int2* sedge; cudaGetSymbolAddress((void**)&sedge, g_sedge);

    // --- A: histogram (first wave) + GEMM (tf32 -> fp16 y) ---
    const int smem_bytes = 2 * 128 * LD * (int)sizeof(unsigned);  // ~135 KB
    cudaFuncSetAttribute(gemm_hist, cudaFuncAttributeMaxDynamicSharedMemorySize,
                         smem_bytes);
    int gblocks = (n + 127) / 128;
    gemm_hist<<<HIST_BLOCKS + gblocks, GEMM_THREADS, smem_bytes>>>(
        x, W, yh, erow, cnt, n, E);

    // --- B: single-block tiled coalesced scan (also zeroes cnt) ---
    fullscan<<<1, SCAN_T>>>(cnt, off, cur, n, E);

    // --- C: permute into row-sorted edge array ---
    permute<<<(E + 511) / 512, 512>>>(erow, ecol, ew, cur, sedge, E);

    // --- D: split-warp gather (one warp per node, 2 edges/iter) ---
    int gthreads = 512;
    int gwpb = gthreads / 32;
    int gblocks2 = (n + gwpb - 1) / gwpb;
    gather<<<gblocks2, gthreads>>>((const uint4*)yh, off, sedge, b,
                                   (float4*)out, n);
}

// round 12
// speedup vs baseline: 2.1792x; 1.4022x over previous
#include <cuda_runtime.h>
#include <cuda_bf16.h>
#include <cuda_fp16.h>
#include <cstdint>

#define N_NODES 50000
#define D 128
#define E_MAX 800000

#define CSR_T 512
#define NB_CSR 98                 // 98*512 = 50176 >= 50000; all co-resident

// ---------------- device scratch (static, no allocation) -------------------
__device__ __half g_y[(size_t)N_NODES * D];       // x @ W^T in fp16 (12.8 MB)
__device__ int    g_cnt[N_NODES];                 // zeroed by csr_build each call
__device__ int    g_off[N_NODES + 1];
__device__ int    g_cur[N_NODES];
__device__ int    g_bsum[NB_CSR];
__device__ int    g_bpre[NB_CSR];
__device__ int2   g_sedge[E_MAX];                 // row-sorted (col, w_bits)

// grid barrier state (generation counter is monotonic across calls)
__device__ unsigned g_barcnt;
__device__ volatile unsigned g_bargen;

// ---------------------------------------------------------------------------
// tf32 mma helpers
// ---------------------------------------------------------------------------
__device__ __forceinline__ unsigned f2tf32(float f) {
    unsigned u;
    asm("cvt.rna.tf32.f32 %0, %1;" : "=r"(u) : "f"(f));
    return u;
}

__device__ __forceinline__ void mma_tf32(float* c, const unsigned* a,
                                         unsigned b0, unsigned b1) {
    asm volatile(
        "mma.sync.aligned.m16n8k8.row.col.f32.tf32.tf32.f32 "
        "{%0,%1,%2,%3}, {%4,%5,%6,%7}, {%8,%9}, {%0,%1,%2,%3};\n"
        : "+f"(c[0]), "+f"(c[1]), "+f"(c[2]), "+f"(c[3])
        : "r"(a[0]), "r"(a[1]), "r"(a[2]), "r"(a[3]), "r"(b0), "r"(b1));
}

#define LD 132
#define GEMM_THREADS 512
#define HIST_BLOCKS 64

// ---------------------------------------------------------------------------
// Kernel A: fused  (a) edge-row histogram  -- FIRST 64 blocks
//                  (b) y = x @ W^T (tf32 tensor cores, fp16 output)
// ---------------------------------------------------------------------------
__global__ void gemm_hist(const float* __restrict__ x,
                          const float* __restrict__ W,
                          __half* __restrict__ yh,
                          const int* __restrict__ erow,
                          int* __restrict__ cnt,
                          int n, int E) {
    if (blockIdx.x < HIST_BLOCKS) {
        int stride = HIST_BLOCKS * GEMM_THREADS;
        int start = blockIdx.x * GEMM_THREADS + threadIdx.x;
        #pragma unroll 4
        for (int e = start; e < E; e += stride)
            atomicAdd(&cnt[__ldg(erow + e)], 1);
        return;
    }

    // ---- GEMM: 128x128 tile, 16 warps (4x4), warp tile 32x32 ----
    extern __shared__ unsigned smem_u[];
    unsigned* As = smem_u;              // [128][LD]
    unsigned* Bs = smem_u + 128 * LD;   // [128][LD]

    int tid = threadIdx.x;
    int row0 = (blockIdx.x - HIST_BLOCKS) * 128;

    for (int i = tid; i < (D * D) / 4; i += GEMM_THREADS) {
        int r = (i * 4) >> 7, c = (i * 4) & 127;
        float4 v = ((const float4*)W)[i];
        unsigned* p = &Bs[r * LD + c];
        p[0] = f2tf32(v.x); p[1] = f2tf32(v.y);
        p[2] = f2tf32(v.z); p[3] = f2tf32(v.w);
    }
    for (int i = tid; i < (128 * D) / 4; i += GEMM_THREADS) {
        int r = (i * 4) >> 7, c = (i * 4) & 127;
        int gr = row0 + r;
        float4 v = (gr < n) ? ((const float4*)(x + (size_t)gr * D))[c >> 2]
                            : make_float4(0.f, 0.f, 0.f, 0.f);
        unsigned* p = &As[r * LD + c];
        p[0] = f2tf32(v.x); p[1] = f2tf32(v.y);
        p[2] = f2tf32(v.z); p[3] = f2tf32(v.w);
    }
    __syncthreads();

    int warp = tid >> 5, lane = tid & 31;
    int wm = warp & 3, wn = warp >> 2;
    int m0 = wm * 32, n0 = wn * 32;
    int grp = lane >> 2, tg = lane & 3;

    float acc[2][4][4];
    #pragma unroll
    for (int mt = 0; mt < 2; mt++)
        #pragma unroll
        for (int nt = 0; nt < 4; nt++)
            #pragma unroll
            for (int q = 0; q < 4; q++) acc[mt][nt][q] = 0.f;

    #pragma unroll
    for (int k0 = 0; k0 < D; k0 += 8) {
        unsigned a[2][4];
        #pragma unroll
        for (int mt = 0; mt < 2; mt++) {
            int r = m0 + mt * 16 + grp;
            a[mt][0] = As[r * LD + k0 + tg];
            a[mt][1] = As[(r + 8) * LD + k0 + tg];
            a[mt][2] = As[r * LD + k0 + tg + 4];
            a[mt][3] = As[(r + 8) * LD + k0 + tg + 4];
        }
        #pragma unroll
        for (int nt = 0; nt < 4; nt++) {
            int nr = n0 + nt * 8 + grp;
            unsigned b0 = Bs[nr * LD + k0 + tg];
            unsigned b1 = Bs[nr * LD + k0 + tg + 4];
            mma_tf32(acc[0][nt], a[0], b0, b1);
            mma_tf32(acc[1][nt], a[1], b0, b1);
        }
    }

    #pragma unroll
    for (int mt = 0; mt < 2; mt++)
        #pragma unroll
        for (int nt = 0; nt < 4; nt++) {
            int r = row0 + m0 + mt * 16 + grp;
            int c = n0 + nt * 8 + tg * 2;
            if (r < n)
                *(__half2*)&yh[(size_t)r * D + c] =
                    __floats2half2_rn(acc[mt][nt][0], acc[mt][nt][1]);
            if (r + 8 < n)
                *(__half2*)&yh[(size_t)(r + 8) * D + c] =
                    __floats2half2_rn(acc[mt][nt][2], acc[mt][nt][3]);
        }
}

// ---------------------------------------------------------------------------
// Kernel B: csr_build — scan + permute in ONE launch with a resident-grid
// barrier (98 blocks x 512 threads, all co-resident on 148 SMs).
//   ph1: per-block inclusive scan of its 512-chunk of cnt (1 elem/thread)
//   ph2: block 0 scans the 98 block totals
//   ph3: write off/cur (global exclusive), zero cnt
//   ph4: grid-stride permute of the 800k edges
// ---------------------------------------------------------------------------
__device__ __forceinline__ int warp_incl_scan(int v, int lane) {
    #pragma unroll
    for (int o = 1; o < 32; o <<= 1) {
        int u = __shfl_up_sync(0xFFFFFFFFu, v, o);
        if (lane >= o) v += u;
    }
    return v;
}

__device__ __forceinline__ void grid_bar() {
    __syncthreads();
    if (threadIdx.x == 0) {
        __threadfence();
        unsigned gen = g_bargen;
        if (atomicAdd(&g_barcnt, 1u) == NB_CSR - 1) {
            g_barcnt = 0;
            __threadfence();
            g_bargen = gen + 1;
        } else {
            while (g_bargen == gen) __nanosleep(64);
        }
        __threadfence();
    }
    __syncthreads();
}

__global__ void csr_build(const int* __restrict__ erow,
                          const int* __restrict__ ecol,
                          const float* __restrict__ ew,
                          int* __restrict__ cnt,
                          int* __restrict__ off,
                          int* __restrict__ cur,
                          int2* __restrict__ sedge,
                          int n, int E) {
    __shared__ int ws[16];
    __shared__ int ws2[16];

    int t = threadIdx.x, b = blockIdx.x;
    int lane = t & 31, wid = t >> 5;
    int i = b * CSR_T + t;

    // ---- ph1: block-local inclusive scan (c kept in register) ----
    int c = (i < n) ? cnt[i] : 0;
    int v = warp_incl_scan(c, lane);
    if (lane == 31) ws[wid] = v;
    __syncthreads();
    if (wid == 0) {
        int s = (lane < 16) ? ws[lane] : 0;
        s = warp_incl_scan(s, lane);
        if (lane < 16) ws[lane] = s;
    }
    __syncthreads();
    int incl = (wid > 0 ? ws[wid - 1] : 0) + v;   // block-inclusive
    if (t == CSR_T - 1) g_bsum[b] = incl;          // block total
    grid_bar();

    // ---- ph2: block 0 scans the NB_CSR block totals ----
    if (b == 0) {
        int cb = (t < NB_CSR) ? g_bsum[t] : 0;
        int vv = warp_incl_scan(cb, lane);
        if (lane == 31) ws2[wid] = vv;
        __syncthreads();
        if (wid == 0) {
            int s = (lane < 16) ? ws2[lane] : 0;
            s = warp_incl_scan(s, lane);
            if (lane < 16) ws2[lane] = s;
        }
        __syncthreads();
        if (t < NB_CSR) g_bpre[t] = (wid > 0 ? ws2[wid - 1] : 0) + vv - cb;
    }
    grid_bar();

    // ---- ph3: write global exclusive offsets, zero cnt ----
    int excl = g_bpre[b] + incl - c;
    if (i < n) {
        off[i] = excl;
        cur[i] = excl;
        cnt[i] = 0;                // ready for next call
    }
    if (i == n) off[n] = E;
    grid_bar();

    // ---- ph4: permute (grid-stride) ----
    int stride = NB_CSR * CSR_T;
    for (int e = b * CSR_T + t; e < E; e += stride) {
        int r = erow[e];
        int p = atomicAdd(&cur[r], 1);
        sedge[p] = make_int2(ecol[e], __float_as_int(ew[e]));
    }
}

// ---------------------------------------------------------------------------
// Kernel C: split-warp gather. One warp per node; 16 lanes per edge,
// two edges per inner iteration. fp16 row = 256 B = 16 uint4 chunks.
// ---------------------------------------------------------------------------
__global__ void gather(const uint4* __restrict__ y4h,
                       const int* __restrict__ off,
                       const int2* __restrict__ sedge,
                       const float* __restrict__ b,
                       float4* __restrict__ out4, int n) {
    int node = (blockIdx.x * blockDim.x + threadIdx.x) >> 5;
    int lane = threadIdx.x & 31;
    if (node >= n) return;

    int hf  = lane >> 4;        // 0: even edges, 1: odd edges
    int sub = lane & 15;        // 16-byte chunk within the 256-byte fp16 row

    int s = off[node];
    int e = off[node + 1];

    float acc[8];
    #pragma unroll
    for (int q = 0; q < 8; q++) acc[q] = 0.f;

    for (int i = s; i < e; i += 32) {
        int j = i + lane;
        int2 ed = (j < e) ? sedge[j] : make_int2(0, 0);
        int cnt = min(32, e - i);
        int pairs = (cnt + 1) >> 1;
        for (int t = 0; t < pairs; t++) {
            int src = 2 * t + hf;
            int col  = __shfl_sync(0xFFFFFFFFu, ed.x, src);
            float w  = __int_as_float(__shfl_sync(0xFFFFFFFFu, ed.y, src));
            uint4 raw = y4h[(size_t)col * 16 + sub];
            float2 f0 = __half22float2(*(const __half2*)&raw.x);
            float2 f1 = __half22float2(*(const __half2*)&raw.y);
            float2 f2 = __half22float2(*(const __half2*)&raw.z);
            float2 f3 = __half22float2(*(const __half2*)&raw.w);
            acc[0] += w * f0.x;  acc[1] += w * f0.y;
            acc[2] += w * f1.x;  acc[3] += w * f1.y;
            acc[4] += w * f2.x;  acc[5] += w * f2.y;
            acc[6] += w * f3.x;  acc[7] += w * f3.y;
        }
    }

    #pragma unroll
    for (int q = 0; q < 8; q++)
        acc[q] += __shfl_xor_sync(0xFFFFFFFFu, acc[q], 16);

    if (hf == 0) {
        const float4* b4 = (const float4*)b;
        float4 bv0 = b4[sub * 2];
        float4 bv1 = b4[sub * 2 + 1];
        float4 o0 = make_float4(acc[0] + bv0.x, acc[1] + bv0.y,
                                acc[2] + bv0.z, acc[3] + bv0.w);
        float4 o1 = make_float4(acc[4] + bv1.x, acc[5] + bv1.y,
                                acc[6] + bv1.z, acc[7] + bv1.w);
        out4[(size_t)node * 32 + sub * 2]     = o0;
        out4[(size_t)node * 32 + sub * 2 + 1] = o1;
    }
}

// ---------------------------------------------------------------------------
extern "C" void kernel_launch(void* const* d_in, const int* in_sizes, int n_in,
                              void* d_out, int out_size) {
    const float* x    = (const float*)d_in[0];
    const int*   erow = (const int*)d_in[1];
    const int*   ecol = (const int*)d_in[2];
    const float* ew   = (const float*)d_in[3];
    const float* W    = (const float*)d_in[4];
    const float* b    = (const float*)d_in[5];
    float* out = (float*)d_out;

    int n = in_sizes[0] / D;     // 50000
    int E = in_sizes[1];         // 800000

    __half* yh;  cudaGetSymbolAddress((void**)&yh, g_y);
    int* cnt;    cudaGetSymbolAddress((void**)&cnt, g_cnt);
    int* off;    cudaGetSymbolAddress((void**)&off, g_off);
    int* cur;    cudaGetSymbolAddress((void**)&cur, g_cur);
    int2* sedge; cudaGetSymbolAddress((void**)&sedge, g_sedge);

    // --- A: histogram (first blocks) + GEMM (tf32 -> fp16 y) ---
    const int smem_bytes = 2 * 128 * LD * (int)sizeof(unsigned);  // ~135 KB
    cudaFuncSetAttribute(gemm_hist, cudaFuncAttributeMaxDynamicSharedMemorySize,
                         smem_bytes);
    int gblocks = (n + 127) / 128;
    gemm_hist<<<HIST_BLOCKS + gblocks, GEMM_THREADS, smem_bytes>>>(
        x, W, yh, erow, cnt, n, E);

    // --- B: scan + permute in one resident-grid kernel ---
    csr_build<<<NB_CSR, CSR_T>>>(erow, ecol, ew, cnt, off, cur, sedge, n, E);

    // --- C: split-warp gather (one warp per node, 2 edges/iter) ---
    int gthreads = 512;
    int gwpb = gthreads / 32;
    int gblocks2 = (n + gwpb - 1) / gwpb;
    gather<<<gblocks2, gthreads>>>((const uint4*)yh, off, sedge, b,
                                   (float4*)out, n);
}

// round 13
// speedup vs baseline: 2.4749x; 1.1357x over previous
#include <cuda_runtime.h>
#include <cuda_bf16.h>
#include <cuda_fp16.h>
#include <cstdint>

#define N_NODES 50000
#define D 128
#define E_MAX 800000

#define CSR_T 512
#define NB_CSR 98                 // 98*512 = 50176 >= 50000; all co-resident

// ---------------- device scratch (static, no allocation) -------------------
__device__ __half g_y[(size_t)N_NODES * D];       // x @ W^T in fp16 (12.8 MB)
__device__ int    g_cnt[N_NODES];                 // zeroed by csr_build each call
__device__ int    g_off[N_NODES + 1];
__device__ int    g_cur[N_NODES];
__device__ int    g_bsum[NB_CSR];
__device__ int    g_bpre[NB_CSR];
__device__ int2   g_sedge[E_MAX];                 // row-sorted (col, w_bits)

// grid barrier state (generation counter is monotonic across calls)
__device__ unsigned g_barcnt;
__device__ volatile unsigned g_bargen;

// ---------------------------------------------------------------------------
// fp16 mma helper: m16n8k16, fp32 accumulate
// ---------------------------------------------------------------------------
__device__ __forceinline__ void mma_f16(float* c, const unsigned* a,
                                        unsigned b0, unsigned b1) {
    asm volatile(
        "mma.sync.aligned.m16n8k16.row.col.f32.f16.f16.f32 "
        "{%0,%1,%2,%3}, {%4,%5,%6,%7}, {%8,%9}, {%0,%1,%2,%3};\n"
        : "+f"(c[0]), "+f"(c[1]), "+f"(c[2]), "+f"(c[3])
        : "r"(a[0]), "r"(a[1]), "r"(a[2]), "r"(a[3]), "r"(b0), "r"(b1));
}

#define LDH 136                   // halfs per row; 68 words ≡ 4 (mod 32) -> CF
#define GEMM_THREADS 512
#define HIST_BLOCKS 64

// ---------------------------------------------------------------------------
// Kernel A: fused  (a) edge-row histogram  -- FIRST 64 blocks
//                  (b) y = x @ W^T via fp16 mma (fp32 accum), fp16 output
// smem = 2 * 128 * 136 * 2B = 68 KB -> 2 CTAs/SM.
// ---------------------------------------------------------------------------
__global__ void gemm_hist(const float* __restrict__ x,
                          const float* __restrict__ W,
                          __half* __restrict__ yh,
                          const int* __restrict__ erow,
                          int* __restrict__ cnt,
                          int n, int E) {
    if (blockIdx.x < HIST_BLOCKS) {
        int stride = HIST_BLOCKS * GEMM_THREADS;
        int start = blockIdx.x * GEMM_THREADS + threadIdx.x;
        #pragma unroll 4
        for (int e = start; e < E; e += stride)
            atomicAdd(&cnt[__ldg(erow + e)], 1);
        return;
    }

    extern __shared__ __half smem_h[];
    __half* As = smem_h;               // [128][LDH]
    __half* Bs = smem_h + 128 * LDH;   // [128][LDH]  (W row-major: [n][k])

    int tid = threadIdx.x;
    int row0 = (blockIdx.x - HIST_BLOCKS) * 128;

    // Fill W tile (fp32 -> fp16)
    for (int i = tid; i < (D * D) / 4; i += GEMM_THREADS) {
        int r = (i * 4) >> 7, c = (i * 4) & 127;
        float4 v = ((const float4*)W)[i];
        __half2* p = (__half2*)&Bs[r * LDH + c];
        p[0] = __floats2half2_rn(v.x, v.y);
        p[1] = __floats2half2_rn(v.z, v.w);
    }
    // Fill A tile (guarded, fp32 -> fp16)
    for (int i = tid; i < (128 * D) / 4; i += GEMM_THREADS) {
        int r = (i * 4) >> 7, c = (i * 4) & 127;
        int gr = row0 + r;
        float4 v = (gr < n) ? ((const float4*)(x + (size_t)gr * D))[c >> 2]
                            : make_float4(0.f, 0.f, 0.f, 0.f);
        __half2* p = (__half2*)&As[r * LDH + c];
        p[0] = __floats2half2_rn(v.x, v.y);
        p[1] = __floats2half2_rn(v.z, v.w);
    }
    __syncthreads();

    int warp = tid >> 5, lane = tid & 31;
    int wm = warp & 3, wn = warp >> 2;         // 4 x 4 warps
    int m0 = wm * 32, n0 = wn * 32;
    int grp = lane >> 2, tg = lane & 3;

    float acc[2][4][4];
    #pragma unroll
    for (int mt = 0; mt < 2; mt++)
        #pragma unroll
        for (int nt = 0; nt < 4; nt++)
            #pragma unroll
            for (int q = 0; q < 4; q++) acc[mt][nt][q] = 0.f;

    #pragma unroll
    for (int k0 = 0; k0 < D; k0 += 16) {
        unsigned a[2][4];
        #pragma unroll
        for (int mt = 0; mt < 2; mt++) {
            int r = m0 + mt * 16 + grp;
            a[mt][0] = *(const unsigned*)&As[r * LDH + k0 + 2 * tg];
            a[mt][1] = *(const unsigned*)&As[(r + 8) * LDH + k0 + 2 * tg];
            a[mt][2] = *(const unsigned*)&As[r * LDH + k0 + 2 * tg + 8];
            a[mt][3] = *(const unsigned*)&As[(r + 8) * LDH + k0 + 2 * tg + 8];
        }
        #pragma unroll
        for (int nt = 0; nt < 4; nt++) {
            int nr = n0 + nt * 8 + grp;
            unsigned b0 = *(const unsigned*)&Bs[nr * LDH + k0 + 2 * tg];
            unsigned b1 = *(const unsigned*)&Bs[nr * LDH + k0 + 2 * tg + 8];
            mma_f16(acc[0][nt], a[0], b0, b1);
            mma_f16(acc[1][nt], a[1], b0, b1);
        }
    }

    #pragma unroll
    for (int mt = 0; mt < 2; mt++)
        #pragma unroll
        for (int nt = 0; nt < 4; nt++) {
            int r = row0 + m0 + mt * 16 + grp;
            int c = n0 + nt * 8 + tg * 2;
            if (r < n)
                *(__half2*)&yh[(size_t)r * D + c] =
                    __floats2half2_rn(acc[mt][nt][0], acc[mt][nt][1]);
            if (r + 8 < n)
                *(__half2*)&yh[(size_t)(r + 8) * D + c] =
                    __floats2half2_rn(acc[mt][nt][2], acc[mt][nt][3]);
        }
}

// ---------------------------------------------------------------------------
// Kernel B: csr_build — scan + permute in ONE launch, resident-grid barrier.
// ---------------------------------------------------------------------------
__device__ __forceinline__ int warp_incl_scan(int v, int lane) {
    #pragma unroll
    for (int o = 1; o < 32; o <<= 1) {
        int u = __shfl_up_sync(0xFFFFFFFFu, v, o);
        if (lane >= o) v += u;
    }
    return v;
}

__device__ __forceinline__ void grid_bar() {
    __syncthreads();
    if (threadIdx.x == 0) {
        __threadfence();
        unsigned gen = g_bargen;
        if (atomicAdd(&g_barcnt, 1u) == NB_CSR - 1) {
            g_barcnt = 0;
            __threadfence();
            g_bargen = gen + 1;
        } else {
            while (g_bargen == gen) __nanosleep(64);
        }
        __threadfence();
    }
    __syncthreads();
}

__global__ void csr_build(const int* __restrict__ erow,
                          const int* __restrict__ ecol,
                          const float* __restrict__ ew,
                          int* __restrict__ cnt,
                          int* __restrict__ off,
                          int* __restrict__ cur,
                          int2* __restrict__ sedge,
                          int n, int E) {
    __shared__ int ws[16];
    __shared__ int ws2[16];

    int t = threadIdx.x, b = blockIdx.x;
    int lane = t & 31, wid = t >> 5;
    int i = b * CSR_T + t;

    // ---- ph1: block-local inclusive scan ----
    int c = (i < n) ? cnt[i] : 0;
    int v = warp_incl_scan(c, lane);
    if (lane == 31) ws[wid] = v;
    __syncthreads();
    if (wid == 0) {
        int s = (lane < 16) ? ws[lane] : 0;
        s = warp_incl_scan(s, lane);
        if (lane < 16) ws[lane] = s;
    }
    __syncthreads();
    int incl = (wid > 0 ? ws[wid - 1] : 0) + v;
    if (t == CSR_T - 1) g_bsum[b] = incl;
    grid_bar();

    // ---- ph2: block 0 scans the block totals ----
    if (b == 0) {
        int cb = (t < NB_CSR) ? g_bsum[t] : 0;
        int vv = warp_incl_scan(cb, lane);
        if (lane == 31) ws2[wid] = vv;
        __syncthreads();
        if (wid == 0) {
            int s = (lane < 16) ? ws2[lane] : 0;
            s = warp_incl_scan(s, lane);
            if (lane < 16) ws2[lane] = s;
        }
        __syncthreads();
        if (t < NB_CSR) g_bpre[t] = (wid > 0 ? ws2[wid - 1] : 0) + vv - cb;
    }
    grid_bar();

    // ---- ph3: write offsets, zero cnt ----
    int excl = g_bpre[b] + incl - c;
    if (i < n) {
        off[i] = excl;
        cur[i] = excl;
        cnt[i] = 0;
    }
    if (i == n) off[n] = E;
    grid_bar();

    // ---- ph4: permute (grid-stride) ----
    int stride = NB_CSR * CSR_T;
    for (int e = b * CSR_T + t; e < E; e += stride) {
        int r = erow[e];
        int p = atomicAdd(&cur[r], 1);
        sedge[p] = make_int2(ecol[e], __float_as_int(ew[e]));
    }
}

// ---------------------------------------------------------------------------
// Kernel C: split-warp gather. One warp per node; 16 lanes per edge,
// two edges per inner iteration. fp16 row = 256 B = 16 uint4 chunks.
// ---------------------------------------------------------------------------
__global__ void gather(const uint4* __restrict__ y4h,
                       const int* __restrict__ off,
                       const int2* __restrict__ sedge,
                       const float* __restrict__ b,
                       float4* __restrict__ out4, int n) {
    int node = (blockIdx.x * blockDim.x + threadIdx.x) >> 5;
    int lane = threadIdx.x & 31;
    if (node >= n) return;

    int hf  = lane >> 4;
    int sub = lane & 15;

    int s = off[node];
    int e = off[node + 1];

    float acc[8];
    #pragma unroll
    for (int q = 0; q < 8; q++) acc[q] = 0.f;

    for (int i = s; i < e; i += 32) {
        int j = i + lane;
        int2 ed = (j < e) ? sedge[j] : make_int2(0, 0);
        int cnt = min(32, e - i);
        int pairs = (cnt + 1) >> 1;
        for (int t = 0; t < pairs; t++) {
            int src = 2 * t + hf;
            int col  = __shfl_sync(0xFFFFFFFFu, ed.x, src);
            float w  = __int_as_float(__shfl_sync(0xFFFFFFFFu, ed.y, src));
            uint4 raw = y4h[(size_t)col * 16 + sub];
            float2 f0 = __half22float2(*(const __half2*)&raw.x);
            float2 f1 = __half22float2(*(const __half2*)&raw.y);
            float2 f2 = __half22float2(*(const __half2*)&raw.z);
            float2 f3 = __half22float2(*(const __half2*)&raw.w);
            acc[0] += w * f0.x;  acc[1] += w * f0.y;
            acc[2] += w * f1.x;  acc[3] += w * f1.y;
            acc[4] += w * f2.x;  acc[5] += w * f2.y;
            acc[6] += w * f3.x;  acc[7] += w * f3.y;
        }
    }

    #pragma unroll
    for (int q = 0; q < 8; q++)
        acc[q] += __shfl_xor_sync(0xFFFFFFFFu, acc[q], 16);

    if (hf == 0) {
        const float4* b4 = (const float4*)b;
        float4 bv0 = b4[sub * 2];
        float4 bv1 = b4[sub * 2 + 1];
        float4 o0 = make_float4(acc[0] + bv0.x, acc[1] + bv0.y,
                                acc[2] + bv0.z, acc[3] + bv0.w);
        float4 o1 = make_float4(acc[4] + bv1.x, acc[5] + bv1.y,
                                acc[6] + bv1.z, acc[7] + bv1.w);
        out4[(size_t)node * 32 + sub * 2]     = o0;
        out4[(size_t)node * 32 + sub * 2 + 1] = o1;
    }
}

// ---------------------------------------------------------------------------
extern "C" void kernel_launch(void* const* d_in, const int* in_sizes, int n_in,
                              void* d_out, int out_size) {
    const float* x    = (const float*)d_in[0];
    const int*   erow = (const int*)d_in[1];
    const int*   ecol = (const int*)d_in[2];
    const float* ew   = (const float*)d_in[3];
    const float* W    = (const float*)d_in[4];
    const float* b    = (const float*)d_in[5];
    float* out = (float*)d_out;

    int n = in_sizes[0] / D;     // 50000
    int E = in_sizes[1];         // 800000

    __half* yh;  cudaGetSymbolAddress((void**)&yh, g_y);
    int* cnt;    cudaGetSymbolAddress((void**)&cnt, g_cnt);
    int* off;    cudaGetSymbolAddress((void**)&off, g_off);
    int* cur;    cudaGetSymbolAddress((void**)&cur, g_cur);
    int2* sedge; cudaGetSymbolAddress((void**)&sedge, g_sedge);

    // --- A: histogram (first blocks) + GEMM (fp16 mma -> fp16 y) ---
    const int smem_bytes = 2 * 128 * LDH * (int)sizeof(__half);  // 68 KB
    cudaFuncSetAttribute(gemm_hist, cudaFuncAttributeMaxDynamicSharedMemorySize,
                         smem_bytes);
    int gblocks = (n + 127) / 128;
    gemm_hist<<<HIST_BLOCKS + gblocks, GEMM_THREADS, smem_bytes>>>(
        x, W, yh, erow, cnt, n, E);

    // --- B: scan + permute in one resident-grid kernel ---
    csr_build<<<NB_CSR, CSR_T>>>(erow, ecol, ew, cnt, off, cur, sedge, n, E);

    // --- C: split-warp gather (one warp per node, 2 edges/iter) ---
    int gthreads = 512;
    int gwpb = gthreads / 32;
    int gblocks2 = (n + gwpb - 1) / gwpb;
    gather<<<gblocks2, gthreads>>>((const uint4*)yh, off, sedge, b,
                                   (float4*)out, n);
}